// round 15
// baseline (speedup 1.0000x reference)
#include <cuda_runtime.h>

#define NX 2048
#define NY 4096
#define ROWS 8
#define FULLMASK 0xffffffffu
typedef unsigned long long ull;

__device__ __forceinline__ ull pk(float lo, float hi) {
    ull r; asm("mov.b64 %0,{%1,%2};" : "=l"(r) : "f"(lo), "f"(hi)); return r;
}
__device__ __forceinline__ void upk(ull p, float& lo, float& hi) {
    asm("mov.b64 {%0,%1},%2;" : "=f"(lo), "=f"(hi) : "l"(p));
}
__device__ __forceinline__ ull fma2(ull a, ull b, ull c) {
    ull d; asm("fma.rn.f32x2 %0,%1,%2,%3;" : "=l"(d) : "l"(a), "l"(b), "l"(c)); return d;
}
__device__ __forceinline__ ull mul2(ull a, ull b) {
    ull d; asm("mul.rn.f32x2 %0,%1,%2;" : "=l"(d) : "l"(a), "l"(b)); return d;
}
__device__ __forceinline__ ull add2(ull a, ull b) {
    ull d; asm("add.rn.f32x2 %0,%1,%2;" : "=l"(d) : "l"(a), "l"(b)); return d;
}
__device__ __forceinline__ ull sub2(ull a, ull b) {
    ull d; asm("sub.rn.f32x2 %0,%1,%2;" : "=l"(d) : "l"(a), "l"(b)); return d;
}
__device__ __forceinline__ ull st3(ull c0, ull f0, ull c1, ull f1, ull c2, ull f2) {
    return fma2(c2, f2, fma2(c1, f1, mul2(c0, f0)));
}

// kind: 0 = left one-sided, 1 = centered, 2 = right one-sided
__device__ __forceinline__ void coeffs_from_inv(float ha, float hb, float inv, int kind,
                                                float c1[3], float c2[3]) {
    float sab = ha + hb;
    float i_a  = hb  * inv;
    float i_ab = sab * inv;
    float i_b  = ha  * inv;
    c2[0] = 2.0f * i_a;
    c2[1] = -2.0f * i_ab;
    c2[2] = 2.0f * i_b;
    if (kind == 0) {
        c1[0] = -(2.0f * ha + hb) * i_a;
        c1[1] = sab * i_ab;
        c1[2] = -ha * i_b;
    } else if (kind == 2) {
        c1[0] = hb * i_a;
        c1[1] = -sab * i_ab;
        c1[2] = (ha + 2.0f * hb) * i_b;
    } else {
        c1[0] = -hb * i_a;
        c1[1] = (hb - ha) * i_ab;
        c1[2] = ha * i_b;
    }
}

// EDGE=false: interior i-blocks — no i-clamps, no firstB/lastB handling.
// 2-deep pipeline: row i+3 load issued at TOP of iteration m (into E),
// consumed by compute at iteration m+2 (~2 full iterations of slack).
template <bool EDGE>
__device__ __forceinline__ void body(const float* __restrict__ u,
                                     const float* __restrict__ v,
                                     const float* __restrict__ xg,
                                     const float* __restrict__ yg,
                                     float mu,
                                     float* __restrict__ out,
                                     int lane, int jW, int j0, int i0) {
    const bool eL = (j0 == 0);
    const bool eR = (j0 == NY - 4);
    const bool firstB = EDGE && (i0 == 0);
    const bool lastB  = EDGE && (i0 == NX - ROWS);

    // ---- rolling window prologue: rows i0-1 .. i0+2 ----
    const int rA = EDGE ? max(i0 - 1, 0) : (i0 - 1);
    float4 Au = *(const float4*)(u + rA * NY + j0);
    float4 Av = *(const float4*)(v + rA * NY + j0);
    float4 Bu = *(const float4*)(u + i0 * NY + j0);
    float4 Bv = *(const float4*)(v + i0 * NY + j0);
    float4 Cu = *(const float4*)(u + (i0 + 1) * NY + j0);
    float4 Cv = *(const float4*)(v + (i0 + 1) * NY + j0);
    float4 Du = *(const float4*)(u + (i0 + 2) * NY + j0);
    float4 Dv = *(const float4*)(v + (i0 + 2) * NY + j0);
    float4 Eu, Ev;

    // ---- warp-edge scalars: one LDG per lane covers all 8 rows x 4 edges ----
    float eDat;
    {
        int mrow = lane & 7;
        int grp  = lane >> 3;
        int ii = i0 + mrow;
        const float* base = (grp & 2) ? v : u;
        int joff = (grp & 1) ? (jW + 128) : (jW - 1);
        bool ok = (joff >= 0) && (joff < NY);
        eDat = ok ? base[ii * NY + (ok ? joff : 0)] : 0.0f;
    }

    // ---- y coefficients (pair-batched: 2 RCPs); mu folded into C2Y; packed ----
    ull C1Y0p01, C1Y0p23, C1Y1p01, C1Y1p23, C1Y2p01, C1Y2p23;
    ull C2Y0p01, C2Y0p23, C2Y1p01, C2Y1p23, C2Y2p01, C2Y2p23;
    {
        float ys[6];
#pragma unroll
        for (int t = 0; t < 6; t++)
            ys[t] = yg[min(max(j0 - 1 + t, 0), NY - 1)];
        float HA[4], HB[4], T[4];
        int KND[4];
#pragma unroll
        for (int l = 0; l < 4; l++) {
            float g0 = ys[l], g1 = ys[l + 1], g2 = ys[l + 2];
            int kind = 1;
            if (l == 0 && eL) { g0 = ys[1]; g1 = ys[2]; g2 = ys[3]; kind = 0; }
            if (l == 3 && eR) { g0 = ys[2]; g1 = ys[3]; g2 = ys[4]; kind = 2; }
            HA[l] = g1 - g0;
            HB[l] = g2 - g1;
            T[l] = HA[l] * HB[l] * (HA[l] + HB[l]);
            KND[l] = kind;
        }
        float ip01 = 1.0f / (T[0] * T[1]);
        float ip23 = 1.0f / (T[2] * T[3]);
        float INV[4] = {ip01 * T[1], ip01 * T[0], ip23 * T[3], ip23 * T[2]};
        float C10[4], C11[4], C12[4], C20[4], C21[4], C22[4];
#pragma unroll
        for (int l = 0; l < 4; l++) {
            float c1[3], c2[3];
            coeffs_from_inv(HA[l], HB[l], INV[l], KND[l], c1, c2);
            C10[l] = c1[0]; C11[l] = c1[1]; C12[l] = c1[2];
            C20[l] = mu * c2[0]; C21[l] = mu * c2[1]; C22[l] = mu * c2[2];
        }
        C1Y0p01 = pk(C10[0], C10[1]); C1Y0p23 = pk(C10[2], C10[3]);
        C1Y1p01 = pk(C11[0], C11[1]); C1Y1p23 = pk(C11[2], C11[3]);
        C1Y2p01 = pk(C12[0], C12[1]); C1Y2p23 = pk(C12[2], C12[3]);
        C2Y0p01 = pk(C20[0], C20[1]); C2Y0p23 = pk(C20[2], C20[3]);
        C2Y1p01 = pk(C21[0], C21[1]); C2Y1p23 = pk(C21[2], C21[3]);
        C2Y2p01 = pk(C22[0], C22[1]); C2Y2p23 = pk(C22[2], C22[3]);
    }
    const ull C001 = pk(0.01f, 0.01f);

    // ---- x coefficients: lane (lane&7) computes one row's set, 1 RCP ----
    float cx1p[3], cx2p[3];
    {
        int ii = i0 + (lane & 7);
        int s, kind;
        if (EDGE) {
            s = min(max(ii - 1, 0), NX - 3);
            kind = (ii == 0) ? 0 : ((ii == NX - 1) ? 2 : 1);
        } else {
            s = ii - 1;
            kind = 1;
        }
        float g0 = xg[s], g1 = xg[s + 1], g2 = xg[s + 2];
        float ha = g1 - g0, hb = g2 - g1;
        float inv = 1.0f / (ha * hb * (ha + hb));
        coeffs_from_inv(ha, hb, inv, kind, cx1p, cx2p);
        cx2p[0] *= mu; cx2p[1] *= mu; cx2p[2] *= mu;
    }

    const float* pu = u + i0 * NY + j0;
    const float* pv = v + i0 * NY + j0;
    float* po = out + i0 * NY + j0;
    float* po2 = po + NX * NY;

#pragma unroll
    for (int m = 0; m < ROWS; m++) {
        // ---- TOP: issue prefetch of row i0+m+3 (consumed at iter m+2) ----
        if (m < ROWS - 2) {
            if (EDGE) {
                int r = min(i0 + m + 3, NX - 1);
                Eu = *(const float4*)(u + r * NY + j0);
                Ev = *(const float4*)(v + r * NY + j0);
            } else {
                Eu = *(const float4*)(pu + 3 * NY);   // row i+3, imm offset
                Ev = *(const float4*)(pv + 3 * NY);
            }
        }

        // x coefficients for this row, broadcast + splatted
        const float cx10 = __shfl_sync(FULLMASK, cx1p[0], m, 8);
        const float cx11 = __shfl_sync(FULLMASK, cx1p[1], m, 8);
        const float cx12 = __shfl_sync(FULLMASK, cx1p[2], m, 8);
        const float cx20 = __shfl_sync(FULLMASK, cx2p[0], m, 8);
        const float cx21 = __shfl_sync(FULLMASK, cx2p[1], m, 8);
        const float cx22 = __shfl_sync(FULLMASK, cx2p[2], m, 8);
        const ull cxp10 = pk(cx10, cx10), cxp11 = pk(cx11, cx11), cxp12 = pk(cx12, cx12);
        const ull cxp20 = pk(cx20, cx20), cxp21 = pk(cx21, cx21), cxp22 = pk(cx22, cx22);

        float4 u0 = Au, u1 = Bu, u2 = Cu;
        float4 v0 = Av, v1 = Bv, v2 = Cv;
        if (EDGE && m == ROWS - 1 && lastB) {   // i==NX-1: rows NX-3,NX-2,NX-1
            float4 zu = *(const float4*)(u + (NX - 3) * NY + j0);
            float4 zv = *(const float4*)(v + (NX - 3) * NY + j0);
            u0 = zu; u1 = Au; u2 = Bu;
            v0 = zv; v1 = Av; v2 = Bv;
        }

        const float4 uc = Bu;
        const float4 vc = Bv;

        // y-neighbors via warp shuffle; edges from staged registers
        float uLm = __shfl_up_sync(FULLMASK, uc.w, 1);
        float vLm = __shfl_up_sync(FULLMASK, vc.w, 1);
        float uRm = __shfl_down_sync(FULLMASK, uc.x, 1);
        float vRm = __shfl_down_sync(FULLMASK, vc.x, 1);
        const float euL = __shfl_sync(FULLMASK, eDat, m);
        const float euR = __shfl_sync(FULLMASK, eDat, 8 + m);
        const float evL = __shfl_sync(FULLMASK, eDat, 16 + m);
        const float evR = __shfl_sync(FULLMASK, eDat, 24 + m);
        if (lane == 0)  { uLm = euL; vLm = evL; }
        if (lane == 31) { uRm = euR; vRm = evR; }

        // ---- packed x stencils ----
        const ull xu0a = pk(u0.x, u0.y), xu0b = pk(u0.z, u0.w);
        const ull xu1a = pk(u1.x, u1.y), xu1b = pk(u1.z, u1.w);
        const ull xu2a = pk(u2.x, u2.y), xu2b = pk(u2.z, u2.w);
        const ull xv0a = pk(v0.x, v0.y), xv0b = pk(v0.z, v0.w);
        const ull xv1a = pk(v1.x, v1.y), xv1b = pk(v1.z, v1.w);
        const ull xv2a = pk(v2.x, v2.y), xv2b = pk(v2.z, v2.w);

        const ull d1xu01 = st3(cxp10, xu0a, cxp11, xu1a, cxp12, xu2a);
        const ull d1xu23 = st3(cxp10, xu0b, cxp11, xu1b, cxp12, xu2b);
        const ull d2xu01 = st3(cxp20, xu0a, cxp21, xu1a, cxp22, xu2a);
        const ull d2xu23 = st3(cxp20, xu0b, cxp21, xu1b, cxp22, xu2b);
        const ull d1xv01 = st3(cxp10, xv0a, cxp11, xv1a, cxp12, xv2a);
        const ull d1xv23 = st3(cxp10, xv0b, cxp11, xv1b, cxp12, xv2b);
        const ull d2xv01 = st3(cxp20, xv0a, cxp21, xv1a, cxp22, xv2a);
        const ull d2xv23 = st3(cxp20, xv0b, cxp21, xv1b, cxp22, xv2b);

        // ---- packed y stencils ----
        const ull ua = pk(uLm, uc.x), ub = pk(uc.x, uc.y), um = pk(uc.y, uc.z),
                  ud = pk(uc.z, uc.w), ue = pk(uc.w, uRm);
        const ull va = pk(vLm, vc.x), vb = pk(vc.x, vc.y), vm = pk(vc.y, vc.z),
                  vd = pk(vc.z, vc.w), ve = pk(vc.w, vRm);

        const ull d1yu01 = st3(C1Y0p01, ua, C1Y1p01, ub, C1Y2p01, um);
        const ull d1yu23 = st3(C1Y0p23, um, C1Y1p23, ud, C1Y2p23, ue);
        const ull d2yu01 = st3(C2Y0p01, ua, C2Y1p01, ub, C2Y2p01, um);
        const ull d2yu23 = st3(C2Y0p23, um, C2Y1p23, ud, C2Y2p23, ue);
        const ull d1yv01 = st3(C1Y0p01, va, C1Y1p01, vb, C1Y2p01, vm);
        const ull d1yv23 = st3(C1Y0p23, vm, C1Y1p23, vd, C1Y2p23, ve);
        const ull d2yv01 = st3(C2Y0p01, va, C2Y1p01, vb, C2Y2p01, vm);
        const ull d2yv23 = st3(C2Y0p23, vm, C2Y1p23, vd, C2Y2p23, ve);

        // ---- combine ----
        const ull duP01 = add2(sub2(sub2(add2(d2yu01, d2xu01), mul2(ub, d1xu01)), mul2(vb, d1yu01)), C001);
        const ull duP23 = add2(sub2(sub2(add2(d2yu23, d2xu23), mul2(ud, d1xu23)), mul2(vd, d1yu23)), C001);
        const ull dvP01 = sub2(sub2(add2(d2yv01, d2xv01), mul2(ub, d1xv01)), mul2(vb, d1yv01));
        const ull dvP23 = sub2(sub2(add2(d2yv23, d2xv23), mul2(ud, d1xv23)), mul2(vd, d1yv23));

        float du0, du1, du2, du3, dv0, dv1, dv2, dv3;
        upk(duP01, du0, du1); upk(duP23, du2, du3);
        upk(dvP01, dv0, dv1); upk(dvP23, dv2, dv3);

        if (eR) {
            float lo, c10, c11, c12, c20, c21, c22, d1x3, d2x3;
            upk(C1Y0p23, lo, c10); upk(C1Y1p23, lo, c11); upk(C1Y2p23, lo, c12);
            upk(C2Y0p23, lo, c20); upk(C2Y1p23, lo, c21); upk(C2Y2p23, lo, c22);
            upk(d1xv23, lo, d1x3); upk(d2xv23, lo, d2x3);
            float d1yR = c10 * vc.y + c11 * vc.z + c12 * vc.w;
            float d2yR = c20 * vc.y + c21 * vc.z + c22 * vc.w;   // mu-scaled
            dv3 = (d2yR + d2x3) - uc.w * d1x3 - vc.w * d1yR;
            du3 = 0.0f;                                           // j == NY-1
        }
        if (eL) { du0 = 0.0f; dv0 = 0.0f; }                       // j == 0
        if (EDGE && m == 0 && firstB) {                           // i == 0
            du0 = du1 = du2 = du3 = 0.0f;
            dv0 = dv1 = dv2 = dv3 = 0.0f;
        }

        *(float4*)po  = make_float4(du0, du1, du2, du3);
        *(float4*)po2 = make_float4(dv0, dv1, dv2, dv3);

        // ---- shift window (E pending from top-of-iteration load) ----
        if (m < ROWS - 1) {
            Au = Bu; Bu = Cu; Cu = Du;
            Av = Bv; Bv = Cv; Cv = Dv;
            if (m < ROWS - 2) { Du = Eu; Dv = Ev; }
            pu += NY; pv += NY; po += NY; po2 += NY;
        }
    }
}

__global__ __launch_bounds__(128, 4) void rhs_kernel(const float* __restrict__ state,
                                                     const float* __restrict__ xg,
                                                     const float* __restrict__ yg,
                                                     const float* __restrict__ mu_p,
                                                     float* __restrict__ out) {
    const int lane = threadIdx.x;
    const int jW = blockIdx.x * 128;
    const int j0 = jW + lane * 4;
    const int it = blockIdx.y * blockDim.y + threadIdx.y;
    const int i0 = it * ROWS;

    const float* u = state;
    const float* v = state + NX * NY;
    const float mu = mu_p[0];

    if (blockIdx.y == 0 || blockIdx.y == gridDim.y - 1) {
        body<true>(u, v, xg, yg, mu, out, lane, jW, j0, i0);
    } else {
        body<false>(u, v, xg, yg, mu, out, lane, jW, j0, i0);
    }
}

extern "C" void kernel_launch(void* const* d_in, const int* in_sizes, int n_in,
                              void* d_out, int out_size) {
    // inputs: 0=t(1), 1=state(2*NX*NY), 2=x(NX), 3=y(NY), 4=mu(1)
    const float* x_g   = (const float*)d_in[2];
    const float* y_g   = (const float*)d_in[3];
    const float* state = (const float*)d_in[1];
    const float* mu    = (const float*)d_in[4];
    float* out = (float*)d_out;

    dim3 blk(32, 4);                          // 128 threads
    dim3 grd((NY / 4) / 32, NX / (4 * ROWS)); // (32, 64)
    rhs_kernel<<<grd, blk>>>(state, x_g, y_g, mu, out);
}

// round 16
// speedup vs baseline: 1.0656x; 1.0656x over previous
#include <cuda_runtime.h>

#define NX 2048
#define NY 4096
#define ROWS 8
#define FULLMASK 0xffffffffu
typedef unsigned long long ull;

__device__ __forceinline__ ull pk(float lo, float hi) {
    ull r; asm("mov.b64 %0,{%1,%2};" : "=l"(r) : "f"(lo), "f"(hi)); return r;
}
__device__ __forceinline__ void upk(ull p, float& lo, float& hi) {
    asm("mov.b64 {%0,%1},%2;" : "=f"(lo), "=f"(hi) : "l"(p));
}
__device__ __forceinline__ ull fma2(ull a, ull b, ull c) {
    ull d; asm("fma.rn.f32x2 %0,%1,%2,%3;" : "=l"(d) : "l"(a), "l"(b), "l"(c)); return d;
}
__device__ __forceinline__ ull mul2(ull a, ull b) {
    ull d; asm("mul.rn.f32x2 %0,%1,%2;" : "=l"(d) : "l"(a), "l"(b)); return d;
}
__device__ __forceinline__ ull add2(ull a, ull b) {
    ull d; asm("add.rn.f32x2 %0,%1,%2;" : "=l"(d) : "l"(a), "l"(b)); return d;
}
__device__ __forceinline__ ull sub2(ull a, ull b) {
    ull d; asm("sub.rn.f32x2 %0,%1,%2;" : "=l"(d) : "l"(a), "l"(b)); return d;
}
__device__ __forceinline__ ull st3(ull c0, ull f0, ull c1, ull f1, ull c2, ull f2) {
    return fma2(c2, f2, fma2(c1, f1, mul2(c0, f0)));
}

// kind: 0 = left one-sided, 1 = centered, 2 = right one-sided
__device__ __forceinline__ void coeffs_from_inv(float ha, float hb, float inv, int kind,
                                                float c1[3], float c2[3]) {
    float sab = ha + hb;
    float i_a  = hb  * inv;
    float i_ab = sab * inv;
    float i_b  = ha  * inv;
    c2[0] = 2.0f * i_a;
    c2[1] = -2.0f * i_ab;
    c2[2] = 2.0f * i_b;
    if (kind == 0) {
        c1[0] = -(2.0f * ha + hb) * i_a;
        c1[1] = sab * i_ab;
        c1[2] = -ha * i_b;
    } else if (kind == 2) {
        c1[0] = hb * i_a;
        c1[1] = -sab * i_ab;
        c1[2] = (ha + 2.0f * hb) * i_b;
    } else {
        c1[0] = -hb * i_a;
        c1[1] = (hb - ha) * i_ab;
        c1[2] = ha * i_b;
    }
}

// EDGE=false: interior i-blocks — no i-clamps, no firstB/lastB handling,
// prefetch via immediate offset (+3*NY), constant centered x-kind.
// Output stores use __stcs (evict-first): output is never re-read, so keep
// it out of L2's working set to preserve state-row residency for reads.
template <bool EDGE>
__device__ __forceinline__ void body(const float* __restrict__ u,
                                     const float* __restrict__ v,
                                     const float* __restrict__ xg,
                                     const float* __restrict__ yg,
                                     float mu,
                                     float* __restrict__ out,
                                     int lane, int jW, int j0, int i0) {
    const bool eL = (j0 == 0);
    const bool eR = (j0 == NY - 4);
    const bool firstB = EDGE && (i0 == 0);
    const bool lastB  = EDGE && (i0 == NX - ROWS);

    // ---- rolling window prologue ----
    const int rA = EDGE ? max(i0 - 1, 0) : (i0 - 1);
    float4 Au = *(const float4*)(u + rA * NY + j0);
    float4 Av = *(const float4*)(v + rA * NY + j0);
    float4 Bu = *(const float4*)(u + i0 * NY + j0);
    float4 Bv = *(const float4*)(v + i0 * NY + j0);
    float4 Cu = *(const float4*)(u + (i0 + 1) * NY + j0);
    float4 Cv = *(const float4*)(v + (i0 + 1) * NY + j0);
    float4 Du = *(const float4*)(u + (i0 + 2) * NY + j0);
    float4 Dv = *(const float4*)(v + (i0 + 2) * NY + j0);

    // ---- warp-edge scalars: one LDG per lane covers all 8 rows x 4 edges ----
    float eDat;
    {
        int mrow = lane & 7;
        int grp  = lane >> 3;
        int ii = i0 + mrow;
        const float* base = (grp & 2) ? v : u;
        int joff = (grp & 1) ? (jW + 128) : (jW - 1);
        bool ok = (joff >= 0) && (joff < NY);
        eDat = ok ? base[ii * NY + (ok ? joff : 0)] : 0.0f;
    }

    // ---- y coefficients (pair-batched: 2 RCPs); mu folded into C2Y; packed ----
    ull C1Y0p01, C1Y0p23, C1Y1p01, C1Y1p23, C1Y2p01, C1Y2p23;
    ull C2Y0p01, C2Y0p23, C2Y1p01, C2Y1p23, C2Y2p01, C2Y2p23;
    {
        float ys[6];
#pragma unroll
        for (int t = 0; t < 6; t++)
            ys[t] = yg[min(max(j0 - 1 + t, 0), NY - 1)];
        float HA[4], HB[4], T[4];
        int KND[4];
#pragma unroll
        for (int l = 0; l < 4; l++) {
            float g0 = ys[l], g1 = ys[l + 1], g2 = ys[l + 2];
            int kind = 1;
            if (l == 0 && eL) { g0 = ys[1]; g1 = ys[2]; g2 = ys[3]; kind = 0; }
            if (l == 3 && eR) { g0 = ys[2]; g1 = ys[3]; g2 = ys[4]; kind = 2; }
            HA[l] = g1 - g0;
            HB[l] = g2 - g1;
            T[l] = HA[l] * HB[l] * (HA[l] + HB[l]);
            KND[l] = kind;
        }
        float ip01 = 1.0f / (T[0] * T[1]);
        float ip23 = 1.0f / (T[2] * T[3]);
        float INV[4] = {ip01 * T[1], ip01 * T[0], ip23 * T[3], ip23 * T[2]};
        float C10[4], C11[4], C12[4], C20[4], C21[4], C22[4];
#pragma unroll
        for (int l = 0; l < 4; l++) {
            float c1[3], c2[3];
            coeffs_from_inv(HA[l], HB[l], INV[l], KND[l], c1, c2);
            C10[l] = c1[0]; C11[l] = c1[1]; C12[l] = c1[2];
            C20[l] = mu * c2[0]; C21[l] = mu * c2[1]; C22[l] = mu * c2[2];
        }
        C1Y0p01 = pk(C10[0], C10[1]); C1Y0p23 = pk(C10[2], C10[3]);
        C1Y1p01 = pk(C11[0], C11[1]); C1Y1p23 = pk(C11[2], C11[3]);
        C1Y2p01 = pk(C12[0], C12[1]); C1Y2p23 = pk(C12[2], C12[3]);
        C2Y0p01 = pk(C20[0], C20[1]); C2Y0p23 = pk(C20[2], C20[3]);
        C2Y1p01 = pk(C21[0], C21[1]); C2Y1p23 = pk(C21[2], C21[3]);
        C2Y2p01 = pk(C22[0], C22[1]); C2Y2p23 = pk(C22[2], C22[3]);
    }
    const ull C001 = pk(0.01f, 0.01f);

    // ---- x coefficients: lane (lane&7) computes one row's set, 1 RCP ----
    float cx1p[3], cx2p[3];
    {
        int ii = i0 + (lane & 7);
        int s, kind;
        if (EDGE) {
            s = min(max(ii - 1, 0), NX - 3);
            kind = (ii == 0) ? 0 : ((ii == NX - 1) ? 2 : 1);
        } else {
            s = ii - 1;
            kind = 1;
        }
        float g0 = xg[s], g1 = xg[s + 1], g2 = xg[s + 2];
        float ha = g1 - g0, hb = g2 - g1;
        float inv = 1.0f / (ha * hb * (ha + hb));
        coeffs_from_inv(ha, hb, inv, kind, cx1p, cx2p);
        cx2p[0] *= mu; cx2p[1] *= mu; cx2p[2] *= mu;
    }

    const float* pu = u + i0 * NY + j0;
    const float* pv = v + i0 * NY + j0;
    float* po = out + i0 * NY + j0;
    float* po2 = po + NX * NY;

#pragma unroll
    for (int m = 0; m < ROWS; m++) {
        // x coefficients for this row, broadcast + splatted
        const float cx10 = __shfl_sync(FULLMASK, cx1p[0], m, 8);
        const float cx11 = __shfl_sync(FULLMASK, cx1p[1], m, 8);
        const float cx12 = __shfl_sync(FULLMASK, cx1p[2], m, 8);
        const float cx20 = __shfl_sync(FULLMASK, cx2p[0], m, 8);
        const float cx21 = __shfl_sync(FULLMASK, cx2p[1], m, 8);
        const float cx22 = __shfl_sync(FULLMASK, cx2p[2], m, 8);
        const ull cxp10 = pk(cx10, cx10), cxp11 = pk(cx11, cx11), cxp12 = pk(cx12, cx12);
        const ull cxp20 = pk(cx20, cx20), cxp21 = pk(cx21, cx21), cxp22 = pk(cx22, cx22);

        float4 u0 = Au, u1 = Bu, u2 = Cu;
        float4 v0 = Av, v1 = Bv, v2 = Cv;
        if (EDGE && m == ROWS - 1 && lastB) {   // i==NX-1: rows NX-3,NX-2,NX-1
            float4 zu = *(const float4*)(u + (NX - 3) * NY + j0);
            float4 zv = *(const float4*)(v + (NX - 3) * NY + j0);
            u0 = zu; u1 = Au; u2 = Bu;
            v0 = zv; v1 = Av; v2 = Bv;
        }

        const float4 uc = Bu;
        const float4 vc = Bv;

        // y-neighbors via warp shuffle; edges from staged registers
        float uLm = __shfl_up_sync(FULLMASK, uc.w, 1);
        float vLm = __shfl_up_sync(FULLMASK, vc.w, 1);
        float uRm = __shfl_down_sync(FULLMASK, uc.x, 1);
        float vRm = __shfl_down_sync(FULLMASK, vc.x, 1);
        const float euL = __shfl_sync(FULLMASK, eDat, m);
        const float euR = __shfl_sync(FULLMASK, eDat, 8 + m);
        const float evL = __shfl_sync(FULLMASK, eDat, 16 + m);
        const float evR = __shfl_sync(FULLMASK, eDat, 24 + m);
        if (lane == 0)  { uLm = euL; vLm = evL; }
        if (lane == 31) { uRm = euR; vRm = evR; }

        // ---- packed x stencils ----
        const ull xu0a = pk(u0.x, u0.y), xu0b = pk(u0.z, u0.w);
        const ull xu1a = pk(u1.x, u1.y), xu1b = pk(u1.z, u1.w);
        const ull xu2a = pk(u2.x, u2.y), xu2b = pk(u2.z, u2.w);
        const ull xv0a = pk(v0.x, v0.y), xv0b = pk(v0.z, v0.w);
        const ull xv1a = pk(v1.x, v1.y), xv1b = pk(v1.z, v1.w);
        const ull xv2a = pk(v2.x, v2.y), xv2b = pk(v2.z, v2.w);

        const ull d1xu01 = st3(cxp10, xu0a, cxp11, xu1a, cxp12, xu2a);
        const ull d1xu23 = st3(cxp10, xu0b, cxp11, xu1b, cxp12, xu2b);
        const ull d2xu01 = st3(cxp20, xu0a, cxp21, xu1a, cxp22, xu2a);
        const ull d2xu23 = st3(cxp20, xu0b, cxp21, xu1b, cxp22, xu2b);
        const ull d1xv01 = st3(cxp10, xv0a, cxp11, xv1a, cxp12, xv2a);
        const ull d1xv23 = st3(cxp10, xv0b, cxp11, xv1b, cxp12, xv2b);
        const ull d2xv01 = st3(cxp20, xv0a, cxp21, xv1a, cxp22, xv2a);
        const ull d2xv23 = st3(cxp20, xv0b, cxp21, xv1b, cxp22, xv2b);

        // ---- packed y stencils ----
        const ull ua = pk(uLm, uc.x), ub = pk(uc.x, uc.y), um = pk(uc.y, uc.z),
                  ud = pk(uc.z, uc.w), ue = pk(uc.w, uRm);
        const ull va = pk(vLm, vc.x), vb = pk(vc.x, vc.y), vm = pk(vc.y, vc.z),
                  vd = pk(vc.z, vc.w), ve = pk(vc.w, vRm);

        const ull d1yu01 = st3(C1Y0p01, ua, C1Y1p01, ub, C1Y2p01, um);
        const ull d1yu23 = st3(C1Y0p23, um, C1Y1p23, ud, C1Y2p23, ue);
        const ull d2yu01 = st3(C2Y0p01, ua, C2Y1p01, ub, C2Y2p01, um);
        const ull d2yu23 = st3(C2Y0p23, um, C2Y1p23, ud, C2Y2p23, ue);
        const ull d1yv01 = st3(C1Y0p01, va, C1Y1p01, vb, C1Y2p01, vm);
        const ull d1yv23 = st3(C1Y0p23, vm, C1Y1p23, vd, C1Y2p23, ve);
        const ull d2yv01 = st3(C2Y0p01, va, C2Y1p01, vb, C2Y2p01, vm);
        const ull d2yv23 = st3(C2Y0p23, vm, C2Y1p23, vd, C2Y2p23, ve);

        // ---- combine ----
        const ull duP01 = add2(sub2(sub2(add2(d2yu01, d2xu01), mul2(ub, d1xu01)), mul2(vb, d1yu01)), C001);
        const ull duP23 = add2(sub2(sub2(add2(d2yu23, d2xu23), mul2(ud, d1xu23)), mul2(vd, d1yu23)), C001);
        const ull dvP01 = sub2(sub2(add2(d2yv01, d2xv01), mul2(ub, d1xv01)), mul2(vb, d1yv01));
        const ull dvP23 = sub2(sub2(add2(d2yv23, d2xv23), mul2(ud, d1xv23)), mul2(vd, d1yv23));

        float du0, du1, du2, du3, dv0, dv1, dv2, dv3;
        upk(duP01, du0, du1); upk(duP23, du2, du3);
        upk(dvP01, dv0, dv1); upk(dvP23, dv2, dv3);

        if (eR) {
            float lo, c10, c11, c12, c20, c21, c22, d1x3, d2x3;
            upk(C1Y0p23, lo, c10); upk(C1Y1p23, lo, c11); upk(C1Y2p23, lo, c12);
            upk(C2Y0p23, lo, c20); upk(C2Y1p23, lo, c21); upk(C2Y2p23, lo, c22);
            upk(d1xv23, lo, d1x3); upk(d2xv23, lo, d2x3);
            float d1yR = c10 * vc.y + c11 * vc.z + c12 * vc.w;
            float d2yR = c20 * vc.y + c21 * vc.z + c22 * vc.w;   // mu-scaled
            dv3 = (d2yR + d2x3) - uc.w * d1x3 - vc.w * d1yR;
            du3 = 0.0f;                                           // j == NY-1
        }
        if (eL) { du0 = 0.0f; dv0 = 0.0f; }                       // j == 0
        if (EDGE && m == 0 && firstB) {                           // i == 0
            du0 = du1 = du2 = du3 = 0.0f;
            dv0 = dv1 = dv2 = dv3 = 0.0f;
        }

        // Streaming (evict-first) stores: output is never re-read.
        __stcs((float4*)po,  make_float4(du0, du1, du2, du3));
        __stcs((float4*)po2, make_float4(dv0, dv1, dv2, dv3));

        // shift window and prefetch next row
        if (m < ROWS - 1) {
            Au = Bu; Bu = Cu; Cu = Du;
            Av = Bv; Bv = Cv; Cv = Dv;
            if (EDGE) {
                int r = min(i0 + m + 3, NX - 1);
                Du = *(const float4*)(u + r * NY + j0);
                Dv = *(const float4*)(v + r * NY + j0);
            } else {
                Du = *(const float4*)(pu + 3 * NY);   // row i+3, imm offset
                Dv = *(const float4*)(pv + 3 * NY);
            }
            pu += NY; pv += NY; po += NY; po2 += NY;
        }
    }
}

__global__ __launch_bounds__(128, 5) void rhs_kernel(const float* __restrict__ state,
                                                     const float* __restrict__ xg,
                                                     const float* __restrict__ yg,
                                                     const float* __restrict__ mu_p,
                                                     float* __restrict__ out) {
    const int lane = threadIdx.x;
    const int jW = blockIdx.x * 128;
    const int j0 = jW + lane * 4;
    const int it = blockIdx.y * blockDim.y + threadIdx.y;
    const int i0 = it * ROWS;

    const float* u = state;
    const float* v = state + NX * NY;
    const float mu = mu_p[0];

    if (blockIdx.y == 0 || blockIdx.y == gridDim.y - 1) {
        body<true>(u, v, xg, yg, mu, out, lane, jW, j0, i0);
    } else {
        body<false>(u, v, xg, yg, mu, out, lane, jW, j0, i0);
    }
}

extern "C" void kernel_launch(void* const* d_in, const int* in_sizes, int n_in,
                              void* d_out, int out_size) {
    // inputs: 0=t(1), 1=state(2*NX*NY), 2=x(NX), 3=y(NY), 4=mu(1)
    const float* x_g   = (const float*)d_in[2];
    const float* y_g   = (const float*)d_in[3];
    const float* state = (const float*)d_in[1];
    const float* mu    = (const float*)d_in[4];
    float* out = (float*)d_out;

    dim3 blk(32, 4);                          // 128 threads
    dim3 grd((NY / 4) / 32, NX / (4 * ROWS)); // (32, 64)
    rhs_kernel<<<grd, blk>>>(state, x_g, y_g, mu, out);
}